// round 8
// baseline (speedup 1.0000x reference)
#include <cuda_runtime.h>
#include <cuda_bf16.h>
#include <cstdint>

#define NN 50000
#define EE 800000
#define HH 256

// ---------------- scratch (device globals; no allocation allowed) ----------
__device__ float g_y[(size_t)NN * HH];
__device__ float g_h[(size_t)NN * HH];
__device__ float g_tx[(size_t)NN * HH];
__device__ float g_tx3[NN * 3];
__device__ float g_pr[128 * HH];
__device__ int   g_deg[NN];
__device__ int   g_off[NN + 1];
__device__ int   g_cur[NN];
__device__ int   g_coldst[EE];
__device__ float g_inv_;
__device__ int   g_flag;
// FFMA2 fallback pre-pack: [L(6)][kt(32)][cb(2)][2560 floats]
__device__ __align__(16) float g_wp[6 * 32 * 2 * 2560];
// HMMA pre-pack: [L(6)][cb(2)][sc(8)][hl(2)][128 n][64 k] bf16
__device__ __align__(16) __nv_bfloat16 g_wm[6 * 2 * 8 * 2 * 8192];

// ---------------- PTX helpers ----------------------------------------------
__device__ __forceinline__ uint32_t smem_u32(const void* p) {
    uint32_t a;
    asm("{ .reg .u64 t; cvta.to.shared.u64 t, %1; cvt.u32.u64 %0, t; }" : "=r"(a) : "l"(p));
    return a;
}
__device__ __forceinline__ void cpa16(uint32_t dst, const void* src) {
    asm volatile("cp.async.ca.shared.global [%0], [%1], 16;\n" ::"r"(dst), "l"(src));
}
__device__ __forceinline__ void ffma2(unsigned long long& d, unsigned long long a,
                                      unsigned long long b) {
    asm("fma.rn.f32x2 %0, %1, %2, %0;" : "+l"(d) : "l"(a), "l"(b));
}
__device__ __forceinline__ void ldmx4(uint32_t& a0, uint32_t& a1, uint32_t& a2,
                                      uint32_t& a3, uint32_t addr) {
    asm volatile("ldmatrix.sync.aligned.m8n8.x4.shared.b16 {%0,%1,%2,%3}, [%4];"
                 : "=r"(a0), "=r"(a1), "=r"(a2), "=r"(a3) : "r"(addr));
}
__device__ __forceinline__ void ldmx2(uint32_t& b0, uint32_t& b1, uint32_t addr) {
    asm volatile("ldmatrix.sync.aligned.m8n8.x2.shared.b16 {%0,%1}, [%2];"
                 : "=r"(b0), "=r"(b1) : "r"(addr));
}
__device__ __forceinline__ void mma16816(float* c, const uint32_t* a, const uint32_t* b) {
    asm volatile(
        "mma.sync.aligned.m16n8k16.row.col.f32.bf16.bf16.f32 "
        "{%0,%1,%2,%3}, {%4,%5,%6,%7}, {%8,%9}, {%0,%1,%2,%3};"
        : "+f"(c[0]), "+f"(c[1]), "+f"(c[2]), "+f"(c[3])
        : "r"(a[0]), "r"(a[1]), "r"(a[2]), "r"(a[3]), "r"(b[0]), "r"(b[1]));
}

// ---------------- CSR build ------------------------------------------------
__global__ void k_zero_deg() {
    int i = blockIdx.x * blockDim.x + threadIdx.x;
    if (i < NN) g_deg[i] = 0;
    if (i == 0) g_flag = 1;
}

__global__ void k_hist(const int* __restrict__ ei) {
    int e = blockIdx.x * blockDim.x + threadIdx.x;
    if (e < EE) atomicAdd(&g_deg[ei[e]], 1);
}

__global__ void k_scan() {
    __shared__ int s[1024];
    __shared__ int mx[1024];
    int t = threadIdx.x;
    const int CH = (NN + 1023) / 1024;
    int lo = t * CH;
    int hi = lo + CH; if (hi > NN) hi = NN; if (lo > NN) lo = NN;
    int sum = 0, m = 0;
    for (int i = lo; i < hi; i++) { int d = g_deg[i]; sum += d; m = max(m, d); }
    s[t] = sum; mx[t] = m;
    __syncthreads();
    for (int o = 1; o < 1024; o <<= 1) {
        int v = (t >= o) ? s[t - o] : 0;
        __syncthreads();
        s[t] += v;
        __syncthreads();
    }
    for (int o = 512; o > 0; o >>= 1) {
        if (t < o) mx[t] = max(mx[t], mx[t + o]);
        __syncthreads();
    }
    int run = s[t] - sum;
    for (int i = lo; i < hi; i++) {
        g_off[i] = run; g_cur[i] = run;
        run += g_deg[i];
    }
    if (t == 1023) g_off[NN] = s[1023];
    if (t == 0)    g_inv_ = 1.0f / (float)mx[0];
}

__global__ void k_bucket(const int* __restrict__ ei) {
    int e = blockIdx.x * blockDim.x + threadIdx.x;
    if (e < EE) {
        int r = ei[e];
        int c = ei[EE + e];
        int p = atomicAdd(&g_cur[r], 1);
        g_coldst[p] = c;
    }
}

// ---------------- FFMA2 weight pre-pack ------------------------------------
__global__ void k_prepw(const float* __restrict__ Wr0, const float* __restrict__ Wr1) {
    int idx = blockIdx.x * blockDim.x + threadIdx.x;
    if (idx >= 6 * 32 * 2 * 512) return;
    int f  = idx & 511;
    int jq = f & 31;
    int kk = f >> 5;
    int cb = (idx >> 9) & 1;
    int kt = (idx >> 10) & 31;
    int L  = idx >> 15;
    const float* B = (kt < 16) ? Wr0 : Wr1;
    int k = ((kt & 15) << 4) + kk;
    const float* src = B + (size_t)L * HH * HH + (size_t)k * HH + (cb << 7) + (jq << 2);
    float4 v = *(const float4*)src;
    int jj = jq << 2;
    int kp = kk >> 1, par = kk & 1;
    float* dst = g_wp + ((size_t)((L * 32 + kt) * 2 + cb)) * 2560
               + kp * 320 + ((jj >> 3) * 20) + ((jj & 7) << 1) + par;
    dst[0] = v.x; dst[2] = v.y; dst[4] = v.z; dst[6] = v.w;
}

// ---------------- HMMA weight pre-pack (bf16 hi/lo, [n][k] row-major) ------
__global__ void k_prepw_mm(const float* __restrict__ Wr0, const float* __restrict__ Wr1) {
    int idx = blockIdx.x * blockDim.x + threadIdx.x;   // 6*2*8*128*16
    if (idx >= 6 * 2 * 8 * 128 * 16) return;
    int kq = idx & 15;
    int n  = (idx >> 4) & 127;
    int sc = (idx >> 11) & 7;
    int cb = (idx >> 14) & 1;
    int L  = idx >> 15;
    union B4 { __nv_bfloat16 h[4]; uint2 u; };
    B4 hi, lo;
#pragma unroll
    for (int i = 0; i < 4; i++) {
        int kg = sc * 64 + kq * 4 + i;
        float w = (kg < 256)
            ? Wr0[(size_t)L * HH * HH + (size_t)kg * HH + cb * 128 + n]
            : Wr1[(size_t)L * HH * HH + (size_t)(kg - 256) * HH + cb * 128 + n];
        __nv_bfloat16 h = __float2bfloat16(w);
        hi.h[i] = h;
        lo.h[i] = __float2bfloat16(w - __bfloat162float(h));
    }
    __nv_bfloat16* base = g_wm + ((size_t)((L * 2 + cb) * 8 + sc)) * 2 * 8192;
    *(uint2*)(base + n * 64 + kq * 4)        = hi.u;
    *(uint2*)(base + 8192 + n * 64 + kq * 4) = lo.u;
}

// ---------------- layer 0 (C_IN = 3) ---------------------------------------
__global__ void k_agg3(const float* __restrict__ x) {
    int i = blockIdx.x * blockDim.x + threadIdx.x;
    if (i >= NN) return;
    int s = g_off[i], e = g_off[i + 1];
    float a0 = 0.f, a1 = 0.f, a2 = 0.f;
    for (int j = s; j < e; j++) {
        int c = g_coldst[j];
        const float* p = x + c * 3;
        a0 += p[0]; a1 += p[1]; a2 += p[2];
    }
    float inv = g_inv_;
    float diag = (float)(e - s) * inv - 1.0f;
    const float* px = x + i * 3;
    g_tx3[i * 3 + 0] = diag * px[0] - inv * a0;
    g_tx3[i * 3 + 1] = diag * px[1] - inv * a1;
    g_tx3[i * 3 + 2] = diag * px[2] - inv * a2;
}

__global__ void k_lin0(const float* __restrict__ x, const float* __restrict__ W0,
                       const float* __restrict__ W1, const float* __restrict__ b) {
    int i = blockIdx.x;
    int j = threadIdx.x;
    __shared__ float sx[3], st[3];
    if (j < 3) { sx[j] = x[i * 3 + j]; st[j] = g_tx3[i * 3 + j]; }
    __syncthreads();
    float v = b[j];
#pragma unroll
    for (int k = 0; k < 3; k++)
        v += sx[k] * W0[k * HH + j] + st[k] * W1[k * HH + j];
    g_y[(size_t)i * HH + j] = fmaxf(v, 0.f);
}

// ---------------- aggregation H=256: warp per (node, 128-ch half) ----------
__global__ void k_agg256(const float* __restrict__ h) {
    int gw   = (blockIdx.x * blockDim.x + threadIdx.x) >> 5;
    int lane = threadIdx.x & 31;
    int node = gw >> 1;
    if (node >= NN) return;
    int cb = ((gw & 1) << 7) + (lane << 2);
    int s = g_off[node], e = g_off[node + 1];
    float4 A0 = make_float4(0, 0, 0, 0), A1 = A0, A2 = A0, A3 = A0;
    int j = s;
    for (; j + 4 <= e; j += 4) {
        int c0 = g_coldst[j], c1 = g_coldst[j + 1], c2 = g_coldst[j + 2], c3 = g_coldst[j + 3];
        float4 v0 = *(const float4*)(h + (size_t)c0 * HH + cb);
        float4 v1 = *(const float4*)(h + (size_t)c1 * HH + cb);
        float4 v2 = *(const float4*)(h + (size_t)c2 * HH + cb);
        float4 v3 = *(const float4*)(h + (size_t)c3 * HH + cb);
        A0.x += v0.x; A0.y += v0.y; A0.z += v0.z; A0.w += v0.w;
        A1.x += v1.x; A1.y += v1.y; A1.z += v1.z; A1.w += v1.w;
        A2.x += v2.x; A2.y += v2.y; A2.z += v2.z; A2.w += v2.w;
        A3.x += v3.x; A3.y += v3.y; A3.z += v3.z; A3.w += v3.w;
    }
    for (; j < e; j++) {
        int c = g_coldst[j];
        float4 v = *(const float4*)(h + (size_t)c * HH + cb);
        A0.x += v.x; A0.y += v.y; A0.z += v.z; A0.w += v.w;
    }
    float4 acc;
    acc.x = (A0.x + A1.x) + (A2.x + A3.x);
    acc.y = (A0.y + A1.y) + (A2.y + A3.y);
    acc.z = (A0.z + A1.z) + (A2.z + A3.z);
    acc.w = (A0.w + A1.w) + (A2.w + A3.w);
    float inv  = g_inv_;
    float diag = (float)(e - s) * inv - 1.0f;
    float4 hx = *(const float4*)(h + (size_t)node * HH + cb);
    float4 o;
    o.x = diag * hx.x - inv * acc.x;
    o.y = diag * hx.y - inv * acc.y;
    o.z = diag * hx.z - inv * acc.z;
    o.w = diag * hx.w - inv * acc.w;
    *(float4*)(g_tx + (size_t)node * HH + cb) = o;
}

// ================= HMMA GEMM (mma.sync bf16 3-term split) ==================
// 128x128 CTA tile, 8 warps (2m x 4n), warp tile 64x32. K=512 in 8 chunks of
// 64. A fp32 -> hi/lo bf16 in-kernel (registers prefetched one chunk ahead);
// B pre-packed hi/lo streamed via cp.async. Rows padded to 144B (no conflicts).
#define ASTR 144
#define MM_SMEM 73728   // 4 regions x 128 rows x 144B

template <bool RELU, bool RES>
__global__ __launch_bounds__(256, 1) void k_gemm_mma(
    const float* __restrict__ A0, const float* __restrict__ A1,
    const __nv_bfloat16* __restrict__ wL,   // &g_wm[L * 2*8*2*8192]
    const float* __restrict__ bias, const float* __restrict__ resid,
    float* __restrict__ out) {
    if (g_flag == 0) return;
    extern __shared__ char sm[];
    uint32_t sb = smem_u32(sm);
    int tid = threadIdx.x, lane = tid & 31, warp = tid >> 5;
    int rowBlk = blockIdx.y * 128, cb = blockIdx.x;
    int wm = (warp >> 2) * 64, wn = (warp & 3) * 32;
    const __nv_bfloat16* wbase = wL + (size_t)cb * 8 * 2 * 8192;

    uint32_t sAh = sb, sBh = sb + 36864;   // AL = +18432, BL = +18432

    float acc[4][4][4];
#pragma unroll
    for (int a = 0; a < 4; a++)
#pragma unroll
        for (int b = 0; b < 4; b++)
#pragma unroll
            for (int c = 0; c < 4; c++) acc[a][b][c] = 0.f;

    // per-lane ldmatrix address components
    int aRow = (lane & 7) + ((lane >> 3) & 1) * 8;  // 0..15
    int aK   = (lane >> 4) * 8;                     // 0 | 8
    int l2   = lane & 15;
    int bN   = l2 & 7;
    int bK   = (l2 >> 3) * 8;

    // A tile: global fp32 -> registers (prefetchable one super-chunk ahead)
    auto loadA = [&](int sc, float4* v) {
        const float* A = (sc < 4) ? A0 : A1;
        int k0 = (sc & 3) << 6;
#pragma unroll
        for (int it = 0; it < 8; it++) {
            int p = tid + (it << 8);       // 0..2047
            int m = p >> 4, kq = p & 15;
            int row = rowBlk + m;
            v[it] = (row < NN) ? *(const float4*)(A + (size_t)row * HH + k0 + kq * 4)
                               : make_float4(0, 0, 0, 0);
        }
    };
    // registers -> hi/lo bf16 -> padded STS
    auto storeA = [&](float4* v) {
#pragma unroll
        for (int it = 0; it < 8; it++) {
            int p = tid + (it << 8);
            int m = p >> 4, kq = p & 15;
            float4 vv = v[it];
            union B4 { __nv_bfloat16 h[4]; uint2 u; };
            B4 hi, lo;
            hi.h[0] = __float2bfloat16(vv.x); hi.h[1] = __float2bfloat16(vv.y);
            hi.h[2] = __float2bfloat16(vv.z); hi.h[3] = __float2bfloat16(vv.w);
            lo.h[0] = __float2bfloat16(vv.x - __bfloat162float(hi.h[0]));
            lo.h[1] = __float2bfloat16(vv.y - __bfloat162float(hi.h[1]));
            lo.h[2] = __float2bfloat16(vv.z - __bfloat162float(hi.h[2]));
            lo.h[3] = __float2bfloat16(vv.w - __bfloat162float(hi.h[3]));
            *(uint2*)(sm + m * ASTR + kq * 8)         = hi.u;
            *(uint2*)(sm + 18432 + m * ASTR + kq * 8) = lo.u;
        }
    };

    float4 va[8], vn[8];
    loadA(0, va);

    for (int sc = 0; sc < 8; sc++) {
        __syncthreads();   // prior iteration's fragments consumed
        // --- B: cp.async hi/lo tiles into padded rows ---
        const char* srcH = (const char*)(wbase + ((size_t)sc * 2 + 0) * 8192);
        const char* srcL = (const char*)(wbase + ((size_t)sc * 2 + 1) * 8192);
#pragma unroll
        for (int u = 0; u < 4; u++) {
            int p = tid + (u << 8);        // 0..1023
            int n = p >> 3, seg = p & 7;
            cpa16(sBh + n * ASTR + seg * 16,         srcH + n * 128 + seg * 16);
            cpa16(sBh + 18432 + n * ASTR + seg * 16, srcL + n * 128 + seg * 16);
        }
        asm volatile("cp.async.commit_group;\n" ::);
        // --- A: convert current chunk, prefetch next chunk's globals ---
        storeA(va);
        if (sc < 7) loadA(sc + 1, vn);   // LDGs overlap wait + compute below
        asm volatile("cp.async.wait_group 0;\n" ::);
        __syncthreads();
        // --- compute 4 k16 steps ---
#pragma unroll
        for (int kt = 0; kt < 4; kt++) {
            uint32_t Ah[4][4], Al[4][4], Bh[4][2], Bl[4][2];
#pragma unroll
            for (int mi = 0; mi < 4; mi++) {
                uint32_t ad = sAh + (uint32_t)(wm + mi * 16 + aRow) * ASTR + (kt * 16 + aK) * 2;
                ldmx4(Ah[mi][0], Ah[mi][1], Ah[mi][2], Ah[mi][3], ad);
                ldmx4(Al[mi][0], Al[mi][1], Al[mi][2], Al[mi][3], ad + 18432);
            }
#pragma unroll
            for (int ni = 0; ni < 4; ni++) {
                uint32_t bd = sBh + (uint32_t)(wn + ni * 8 + bN) * ASTR + (kt * 16 + bK) * 2;
                ldmx2(Bh[ni][0], Bh[ni][1], bd);
                ldmx2(Bl[ni][0], Bl[ni][1], bd + 18432);
            }
#pragma unroll
            for (int mi = 0; mi < 4; mi++)
#pragma unroll
                for (int ni = 0; ni < 4; ni++) {
                    mma16816(acc[mi][ni], Ah[mi], Bh[ni]);
                    mma16816(acc[mi][ni], Al[mi], Bh[ni]);
                    mma16816(acc[mi][ni], Ah[mi], Bl[ni]);
                }
        }
#pragma unroll
        for (int it = 0; it < 8; it++) va[it] = vn[it];
    }
    // --- epilogue ---
#pragma unroll
    for (int mi = 0; mi < 4; mi++) {
        int r0 = rowBlk + wm + mi * 16 + (lane >> 2);
        int r1 = r0 + 8;
#pragma unroll
        for (int ni = 0; ni < 4; ni++) {
            int col = cb * 128 + wn + ni * 8 + (lane & 3) * 2;
            float b0 = bias[col], b1 = bias[col + 1];
            float* c = acc[mi][ni];
            if (r0 < NN) {
                float v0 = c[0] + b0, v1 = c[1] + b1;
                if (RELU) { v0 = fmaxf(v0, 0.f); v1 = fmaxf(v1, 0.f); }
                if (RES) {
                    v0 = 0.5f * (resid[(size_t)r0 * HH + col] + v0);
                    v1 = 0.5f * (resid[(size_t)r0 * HH + col + 1] + v1);
                }
                *(float2*)(out + (size_t)r0 * HH + col) = make_float2(v0, v1);
            }
            if (r1 < NN) {
                float v2 = c[2] + b0, v3 = c[3] + b1;
                if (RELU) { v2 = fmaxf(v2, 0.f); v3 = fmaxf(v3, 0.f); }
                if (RES) {
                    v2 = 0.5f * (resid[(size_t)r1 * HH + col] + v2);
                    v3 = 0.5f * (resid[(size_t)r1 * HH + col + 1] + v3);
                }
                *(float2*)(out + (size_t)r1 * HH + col) = make_float2(v2, v3);
            }
        }
    }
}

// ---- probe: fp32 reference of layer-0 GEMM rows 0..127, all 256 cols ------
__global__ void k_pref(const float* __restrict__ W0, const float* __restrict__ W1,
                       const float* __restrict__ b) {
    int m = blockIdx.x, n = threadIdx.x;
    float s = b[n];
    const float* y = g_y + (size_t)m * HH;
    const float* t = g_tx + (size_t)m * HH;
    for (int k = 0; k < HH; k++)
        s += y[k] * W0[(size_t)k * HH + n] + t[k] * W1[(size_t)k * HH + n];
    g_pr[m * HH + n] = fmaxf(s, 0.f);
}

__global__ void k_cmp() {
    int i = blockIdx.x * blockDim.x + threadIdx.x;
    if (i >= 128 * HH) return;
    float a = g_h[i];
    float b = g_pr[i];
    // catches structural/layout failures (O(1) garbage); tolerant of split-bf16 noise
    if (fabsf(a - b) > 1e-3f * fabsf(b) + 2e-4f) g_flag = 0;
}

// ================= FFMA2 fallback GEMM (audited R2 design) =================
template <bool RELU, bool RES>
__global__ __launch_bounds__(256, 1) void k_gemm(
    const float* __restrict__ A0, const float* __restrict__ A1,
    const float* __restrict__ wp, const float* __restrict__ bias,
    const float* __restrict__ resid, float* __restrict__ out) {
    if (g_flag == 1) return;
    __shared__ __align__(16) float As[2][2048];
    __shared__ __align__(16) float Bs[2][2560];
    int tid = threadIdx.x;
    int rowBlk = blockIdx.y * 128;
    int colBlk = blockIdx.x * 128;
    int cbi = blockIdx.x;
    int tr = tid >> 4, tc = tid & 15;

    unsigned long long acc[8][8];
#pragma unroll
    for (int i = 0; i < 8; i++)
#pragma unroll
        for (int j = 0; j < 8; j++) acc[i][j] = 0ull;

    auto issueB = [&](int kt, int buf) {
        const char* src = (const char*)(wp + ((size_t)(kt * 2 + cbi)) * 2560);
        uint32_t dst = smem_u32(&Bs[buf][0]);
        cpa16(dst + tid * 16,        src + tid * 16);
        cpa16(dst + 4096 + tid * 16, src + 4096 + tid * 16);
        if (tid < 128) cpa16(dst + 8192 + tid * 16, src + 8192 + tid * 16);
        asm volatile("cp.async.commit_group;\n" ::);
    };
    auto loadA = [&](int kt, float4* pa) {
        const float* A = (kt < 16) ? A0 : A1;
        int k0 = (kt & 15) << 4;
#pragma unroll
        for (int it = 0; it < 2; it++) {
            int p = tid + (it << 8);
            int m = p >> 2, kq = (p & 3) << 2;
            int row = rowBlk + m;
            pa[it] = (row < NN) ? *(const float4*)(A + (size_t)row * HH + k0 + kq)
                                : make_float4(0, 0, 0, 0);
        }
    };
    auto storeA = [&](int buf, float4* pa) {
#pragma unroll
        for (int it = 0; it < 2; it++) {
            int p = tid + (it << 8);
            int m = p >> 2, kq = (p & 3) << 2;
            float4 v = pa[it];
            *(float2*)&As[buf][(kq >> 1) * 256 + (m << 1)]       = make_float2(v.x, v.y);
            *(float2*)&As[buf][((kq >> 1) + 1) * 256 + (m << 1)] = make_float2(v.z, v.w);
        }
    };

    float4 ra[2];
    issueB(0, 0);
    loadA(0, ra);
    storeA(0, ra);
    asm volatile("cp.async.wait_group 0;\n" ::);
    __syncthreads();

    for (int kt = 0; kt < 32; kt++) {
        int buf = kt & 1;
        float4 na[2];
        if (kt < 31) {
            issueB(kt + 1, buf ^ 1);
            loadA(kt + 1, na);
        }
#pragma unroll
        for (int kp = 0; kp < 8; kp++) {
            const ulonglong2* ap = (const ulonglong2*)&As[buf][kp * 256 + (tr << 4)];
            const ulonglong2* bp = (const ulonglong2*)&Bs[buf][kp * 320 + tc * 20];
            unsigned long long a[8], b[8];
#pragma unroll
            for (int u = 0; u < 4; u++) { ulonglong2 t2 = ap[u]; a[2 * u] = t2.x; a[2 * u + 1] = t2.y; }
#pragma unroll
            for (int u = 0; u < 4; u++) { ulonglong2 t2 = bp[u]; b[2 * u] = t2.x; b[2 * u + 1] = t2.y; }
#pragma unroll
            for (int i = 0; i < 8; i++)
#pragma unroll
                for (int j = 0; j < 8; j++) ffma2(acc[i][j], a[i], b[j]);
        }
        if (kt < 31) {
            storeA(buf ^ 1, na);
            asm volatile("cp.async.wait_group 0;\n" ::);
        }
        __syncthreads();
    }

#pragma unroll
    for (int i = 0; i < 8; i++) {
        int row = rowBlk + (tr << 3) + i;
        if (row >= NN) continue;
        float vals[8];
#pragma unroll
        for (int j = 0; j < 8; j++) {
            unsigned long long u = acc[i][j];
            float loF = __uint_as_float((unsigned)(u & 0xffffffffu));
            float hiF = __uint_as_float((unsigned)(u >> 32));
            int col = colBlk + (tc << 3) + j;
            float v = loF + hiF + bias[col];
            if (RELU) v = fmaxf(v, 0.f);
            if (RES)  v = 0.5f * (resid[(size_t)row * HH + col] + v);
            vals[j] = v;
        }
        float* op = out + (size_t)row * HH + colBlk + (tc << 3);
        *(float4*)op       = make_float4(vals[0], vals[1], vals[2], vals[3]);
        *(float4*)(op + 4) = make_float4(vals[4], vals[5], vals[6], vals[7]);
    }
}

// ---------------- final layer (C_OUT = 3) + fused y copy -------------------
__global__ void k_final(const float* __restrict__ W0, const float* __restrict__ W1,
                        const float* __restrict__ bf, float* __restrict__ out) {
    __shared__ float w0[HH * 3], w1[HH * 3];
    int tid = threadIdx.x;
    for (int i = tid; i < HH * 3; i += 256) { w0[i] = W0[i]; w1[i] = W1[i]; }
    __syncthreads();
    int warp = tid >> 5, lane = tid & 31;
    int node = blockIdx.x * 8 + warp;
    if (node >= NN) return;
    const float* y  = g_y  + (size_t)node * HH;
    const float* tx = g_tx + (size_t)node * HH;
    float* ycopy = out + NN * 3 + (size_t)node * HH;
    float p0 = 0.f, p1 = 0.f, p2 = 0.f;
#pragma unroll
    for (int u = 0; u < 8; u++) {
        int k = lane * 8 + u;
        float yv = y[k], tv = tx[k];
        ycopy[k] = yv;
        p0 += yv * w0[k * 3 + 0] + tv * w1[k * 3 + 0];
        p1 += yv * w0[k * 3 + 1] + tv * w1[k * 3 + 1];
        p2 += yv * w0[k * 3 + 2] + tv * w1[k * 3 + 2];
    }
#pragma unroll
    for (int o = 16; o > 0; o >>= 1) {
        p0 += __shfl_xor_sync(0xffffffffu, p0, o);
        p1 += __shfl_xor_sync(0xffffffffu, p1, o);
        p2 += __shfl_xor_sync(0xffffffffu, p2, o);
    }
    if (lane == 0) {
        out[node * 3 + 0] = p0 + bf[0];
        out[node * 3 + 1] = p1 + bf[1];
        out[node * 3 + 2] = p2 + bf[2];
    }
}

// ---------------- launch ---------------------------------------------------
extern "C" void kernel_launch(void* const* d_in, const int* in_sizes, int n_in,
                              void* d_out, int out_size) {
    (void)in_sizes; (void)n_in; (void)out_size;
    const float* x   = (const float*)d_in[0];
    const int*   ei  = (const int*)d_in[1];
    const float* Wi0 = (const float*)d_in[2];
    const float* Wi1 = (const float*)d_in[3];
    const float* bi  = (const float*)d_in[4];
    const float* Wr0 = (const float*)d_in[5];
    const float* Wr1 = (const float*)d_in[6];
    const float* br  = (const float*)d_in[7];
    const float* Wf0 = (const float*)d_in[8];
    const float* Wf1 = (const float*)d_in[9];
    const float* bf  = (const float*)d_in[10];
    float* out = (float*)d_out;

    float *py, *ph, *ptx, *pwp;
    __nv_bfloat16* pwm;
    cudaGetSymbolAddress((void**)&py,  g_y);
    cudaGetSymbolAddress((void**)&ph,  g_h);
    cudaGetSymbolAddress((void**)&ptx, g_tx);
    cudaGetSymbolAddress((void**)&pwp, g_wp);
    cudaGetSymbolAddress((void**)&pwm, g_wm);

    cudaFuncSetAttribute(k_gemm_mma<true, false>, cudaFuncAttributeMaxDynamicSharedMemorySize, MM_SMEM);
    cudaFuncSetAttribute(k_gemm_mma<true, true>,  cudaFuncAttributeMaxDynamicSharedMemorySize, MM_SMEM);

    k_zero_deg<<<(NN + 255) / 256, 256>>>();
    k_hist<<<(EE + 255) / 256, 256>>>(ei);
    k_prepw<<<(6 * 32 * 2 * 512 + 255) / 256, 256>>>(Wr0, Wr1);
    k_prepw_mm<<<(6 * 2 * 8 * 128 * 16 + 255) / 256, 256>>>(Wr0, Wr1);
    k_scan<<<1, 1024>>>();
    k_bucket<<<(EE + 255) / 256, 256>>>(ei);

    k_agg3<<<(NN + 255) / 256, 256>>>(x);
    k_lin0<<<NN, 256>>>(x, Wi0, Wi1, bi);

    dim3 ggrid(2, (NN + 127) / 128);
    int aggBlocks = (NN * 2) / 8;
    const size_t WSZ  = (size_t)32 * 2 * 2560;
    const size_t WMSZ = (size_t)2 * 8 * 2 * 8192;

    // ---- layer pair 0, with self-validation after the first HMMA GEMM ----
    k_agg256<<<aggBlocks, 256>>>(py);
    k_gemm_mma<true, false><<<ggrid, 256, MM_SMEM>>>(py, ptx, pwm + 0 * WMSZ, br + 0, nullptr, ph);
    k_pref<<<128, 256>>>(Wr0, Wr1, br);
    k_cmp<<<(128 * HH + 255) / 256, 256>>>();
    k_gemm<true, false><<<ggrid, 256>>>(py, ptx, pwp + 0 * WSZ, br + 0, nullptr, ph);

    k_agg256<<<aggBlocks, 256>>>(ph);
    k_gemm_mma<true, true><<<ggrid, 256, MM_SMEM>>>(ph, ptx, pwm + 1 * WMSZ, br + 1 * HH, py, py);
    k_gemm<true, true><<<ggrid, 256>>>(ph, ptx, pwp + 1 * WSZ, br + 1 * HH, py, py);

    for (int blk = 1; blk < 3; blk++) {
        int L0 = 2 * blk, L1 = 2 * blk + 1;
        k_agg256<<<aggBlocks, 256>>>(py);
        k_gemm_mma<true, false><<<ggrid, 256, MM_SMEM>>>(py, ptx, pwm + (size_t)L0 * WMSZ, br + L0 * HH, nullptr, ph);
        k_gemm<true, false><<<ggrid, 256>>>(py, ptx, pwp + (size_t)L0 * WSZ, br + L0 * HH, nullptr, ph);
        k_agg256<<<aggBlocks, 256>>>(ph);
        k_gemm_mma<true, true><<<ggrid, 256, MM_SMEM>>>(ph, ptx, pwm + (size_t)L1 * WMSZ, br + L1 * HH, py, py);
        k_gemm<true, true><<<ggrid, 256>>>(ph, ptx, pwp + (size_t)L1 * WSZ, br + L1 * HH, py, py);
    }
    k_agg256<<<aggBlocks, 256>>>(py);
    k_final<<<(NN + 7) / 8, 256>>>(Wf0, Wf1, bf, out);
}

// round 15
// speedup vs baseline: 1.0459x; 1.0459x over previous
#include <cuda_runtime.h>
#include <cuda_bf16.h>
#include <cstdint>

#define NN 50000
#define EE 800000
#define HH 256

// ---------------- scratch (device globals; no allocation allowed) ----------
__device__ float g_y[(size_t)NN * HH];
__device__ float g_h[(size_t)NN * HH];
__device__ float g_tx[(size_t)NN * HH];
__device__ float g_tx3[NN * 3];
__device__ int   g_deg[NN];
__device__ int   g_off[NN + 1];
__device__ int   g_cur[NN];
__device__ int   g_coldst[EE];
__device__ float g_inv_;
// HMMA pre-pack: [L(6)][cb(2)][sc(8)][hl(2)][128 n][64 k] bf16
__device__ __align__(16) __nv_bfloat16 g_wm[6 * 2 * 8 * 2 * 8192];

// ---------------- PTX helpers ----------------------------------------------
__device__ __forceinline__ uint32_t smem_u32(const void* p) {
    uint32_t a;
    asm("{ .reg .u64 t; cvta.to.shared.u64 t, %1; cvt.u32.u64 %0, t; }" : "=r"(a) : "l"(p));
    return a;
}
__device__ __forceinline__ void cpa16(uint32_t dst, const void* src) {
    asm volatile("cp.async.ca.shared.global [%0], [%1], 16;\n" ::"r"(dst), "l"(src));
}
__device__ __forceinline__ void ldmx4(uint32_t& a0, uint32_t& a1, uint32_t& a2,
                                      uint32_t& a3, uint32_t addr) {
    asm volatile("ldmatrix.sync.aligned.m8n8.x4.shared.b16 {%0,%1,%2,%3}, [%4];"
                 : "=r"(a0), "=r"(a1), "=r"(a2), "=r"(a3) : "r"(addr));
}
__device__ __forceinline__ void ldmx2(uint32_t& b0, uint32_t& b1, uint32_t addr) {
    asm volatile("ldmatrix.sync.aligned.m8n8.x2.shared.b16 {%0,%1}, [%2];"
                 : "=r"(b0), "=r"(b1) : "r"(addr));
}
__device__ __forceinline__ void mma16816(float* c, const uint32_t* a, const uint32_t* b) {
    asm volatile(
        "mma.sync.aligned.m16n8k16.row.col.f32.bf16.bf16.f32 "
        "{%0,%1,%2,%3}, {%4,%5,%6,%7}, {%8,%9}, {%0,%1,%2,%3};"
        : "+f"(c[0]), "+f"(c[1]), "+f"(c[2]), "+f"(c[3])
        : "r"(a[0]), "r"(a[1]), "r"(a[2]), "r"(a[3]), "r"(b[0]), "r"(b[1]));
}

// ---------------- CSR build ------------------------------------------------
__global__ void k_zero_deg() {
    int i = blockIdx.x * blockDim.x + threadIdx.x;
    if (i < NN) g_deg[i] = 0;
}

__global__ void k_hist(const int* __restrict__ ei) {
    int e = blockIdx.x * blockDim.x + threadIdx.x;
    if (e < EE) atomicAdd(&g_deg[ei[e]], 1);
}

__global__ void k_scan() {
    __shared__ int s[1024];
    __shared__ int mx[1024];
    int t = threadIdx.x;
    const int CH = (NN + 1023) / 1024;
    int lo = t * CH;
    int hi = lo + CH; if (hi > NN) hi = NN; if (lo > NN) lo = NN;
    int sum = 0, m = 0;
    for (int i = lo; i < hi; i++) { int d = g_deg[i]; sum += d; m = max(m, d); }
    s[t] = sum; mx[t] = m;
    __syncthreads();
    for (int o = 1; o < 1024; o <<= 1) {
        int v = (t >= o) ? s[t - o] : 0;
        __syncthreads();
        s[t] += v;
        __syncthreads();
    }
    for (int o = 512; o > 0; o >>= 1) {
        if (t < o) mx[t] = max(mx[t], mx[t + o]);
        __syncthreads();
    }
    int run = s[t] - sum;
    for (int i = lo; i < hi; i++) {
        g_off[i] = run; g_cur[i] = run;
        run += g_deg[i];
    }
    if (t == 1023) g_off[NN] = s[1023];
    if (t == 0)    g_inv_ = 1.0f / (float)mx[0];
}

__global__ void k_bucket(const int* __restrict__ ei) {
    int e = blockIdx.x * blockDim.x + threadIdx.x;
    if (e < EE) {
        int r = ei[e];
        int c = ei[EE + e];
        int p = atomicAdd(&g_cur[r], 1);
        g_coldst[p] = c;
    }
}

// ---------------- HMMA weight pre-pack (bf16 hi/lo, [n][k] row-major) ------
__global__ void k_prepw_mm(const float* __restrict__ Wr0, const float* __restrict__ Wr1) {
    int idx = blockIdx.x * blockDim.x + threadIdx.x;   // 6*2*8*128*16
    if (idx >= 6 * 2 * 8 * 128 * 16) return;
    int kq = idx & 15;
    int n  = (idx >> 4) & 127;
    int sc = (idx >> 11) & 7;
    int cb = (idx >> 14) & 1;
    int L  = idx >> 15;
    union B4 { __nv_bfloat16 h[4]; uint2 u; };
    B4 hi, lo;
#pragma unroll
    for (int i = 0; i < 4; i++) {
        int kg = sc * 64 + kq * 4 + i;
        float w = (kg < 256)
            ? Wr0[(size_t)L * HH * HH + (size_t)kg * HH + cb * 128 + n]
            : Wr1[(size_t)L * HH * HH + (size_t)(kg - 256) * HH + cb * 128 + n];
        __nv_bfloat16 h = __float2bfloat16(w);
        hi.h[i] = h;
        lo.h[i] = __float2bfloat16(w - __bfloat162float(h));
    }
    __nv_bfloat16* base = g_wm + ((size_t)((L * 2 + cb) * 8 + sc)) * 2 * 8192;
    *(uint2*)(base + n * 64 + kq * 4)        = hi.u;
    *(uint2*)(base + 8192 + n * 64 + kq * 4) = lo.u;
}

// ---------------- layer 0 (C_IN = 3) ---------------------------------------
__global__ void k_agg3(const float* __restrict__ x) {
    int i = blockIdx.x * blockDim.x + threadIdx.x;
    if (i >= NN) return;
    int s = g_off[i], e = g_off[i + 1];
    float a0 = 0.f, a1 = 0.f, a2 = 0.f;
    for (int j = s; j < e; j++) {
        int c = g_coldst[j];
        const float* p = x + c * 3;
        a0 += p[0]; a1 += p[1]; a2 += p[2];
    }
    float inv = g_inv_;
    float diag = (float)(e - s) * inv - 1.0f;
    const float* px = x + i * 3;
    g_tx3[i * 3 + 0] = diag * px[0] - inv * a0;
    g_tx3[i * 3 + 1] = diag * px[1] - inv * a1;
    g_tx3[i * 3 + 2] = diag * px[2] - inv * a2;
}

// warp-per-node, 8 cols/lane; weights staged in smem
__global__ __launch_bounds__(256) void k_lin0(
    const float* __restrict__ x, const float* __restrict__ W0,
    const float* __restrict__ W1, const float* __restrict__ b) {
    __shared__ float w0[3 * HH], w1[3 * HH], bb[HH];
    int tid = threadIdx.x;
    for (int i = tid; i < 3 * HH; i += 256) { w0[i] = W0[i]; w1[i] = W1[i]; }
    if (tid < HH) bb[tid] = b[tid];
    __syncthreads();
    int warp = tid >> 5, lane = tid & 31;
    int node = blockIdx.x * 8 + warp;
    if (node >= NN) return;
    float x0 = x[node * 3], x1 = x[node * 3 + 1], x2 = x[node * 3 + 2];
    float t0 = g_tx3[node * 3], t1 = g_tx3[node * 3 + 1], t2 = g_tx3[node * 3 + 2];
    float* yp = g_y + (size_t)node * HH;
#pragma unroll
    for (int u = 0; u < 2; u++) {
        int col = lane * 4 + u * 128;
        float4 o;
        float* po = &o.x;
#pragma unroll
        for (int q = 0; q < 4; q++) {
            int c = col + q;
            po[q] = fmaxf(bb[c] + x0 * w0[c] + x1 * w0[HH + c] + x2 * w0[2 * HH + c]
                                + t0 * w1[c] + t1 * w1[HH + c] + t2 * w1[2 * HH + c], 0.f);
        }
        *(float4*)(yp + col) = o;
    }
}

// ---------------- aggregation H=256: warp per (node, 128-ch half) ----------
__global__ void k_agg256(const float* __restrict__ h) {
    int gw   = (blockIdx.x * blockDim.x + threadIdx.x) >> 5;
    int lane = threadIdx.x & 31;
    int node = gw >> 1;
    if (node >= NN) return;
    int cb = ((gw & 1) << 7) + (lane << 2);
    int s = g_off[node], e = g_off[node + 1];
    float4 A0 = make_float4(0, 0, 0, 0), A1 = A0, A2 = A0, A3 = A0;
    int j = s;
    for (; j + 4 <= e; j += 4) {
        int c0 = g_coldst[j], c1 = g_coldst[j + 1], c2 = g_coldst[j + 2], c3 = g_coldst[j + 3];
        float4 v0 = *(const float4*)(h + (size_t)c0 * HH + cb);
        float4 v1 = *(const float4*)(h + (size_t)c1 * HH + cb);
        float4 v2 = *(const float4*)(h + (size_t)c2 * HH + cb);
        float4 v3 = *(const float4*)(h + (size_t)c3 * HH + cb);
        A0.x += v0.x; A0.y += v0.y; A0.z += v0.z; A0.w += v0.w;
        A1.x += v1.x; A1.y += v1.y; A1.z += v1.z; A1.w += v1.w;
        A2.x += v2.x; A2.y += v2.y; A2.z += v2.z; A2.w += v2.w;
        A3.x += v3.x; A3.y += v3.y; A3.z += v3.z; A3.w += v3.w;
    }
    for (; j < e; j++) {
        int c = g_coldst[j];
        float4 v = *(const float4*)(h + (size_t)c * HH + cb);
        A0.x += v.x; A0.y += v.y; A0.z += v.z; A0.w += v.w;
    }
    float4 acc;
    acc.x = (A0.x + A1.x) + (A2.x + A3.x);
    acc.y = (A0.y + A1.y) + (A2.y + A3.y);
    acc.z = (A0.z + A1.z) + (A2.z + A3.z);
    acc.w = (A0.w + A1.w) + (A2.w + A3.w);
    float inv  = g_inv_;
    float diag = (float)(e - s) * inv - 1.0f;
    float4 hx = *(const float4*)(h + (size_t)node * HH + cb);
    float4 o;
    o.x = diag * hx.x - inv * acc.x;
    o.y = diag * hx.y - inv * acc.y;
    o.z = diag * hx.z - inv * acc.z;
    o.w = diag * hx.w - inv * acc.w;
    *(float4*)(g_tx + (size_t)node * HH + cb) = o;
}

// ================= HMMA GEMM (mma.sync bf16 3-term split) ==================
// 128x128 CTA tile, 8 warps (2m x 4n), warp tile 64x32. K=512 in 8 chunks of
// 64. Fully double-buffered smem (2 x 73728B): one __syncthreads per chunk;
// B cp.async + A convert/STS for chunk sc+1 overlap compute of chunk sc.
#define ASTR 144
#define BUFSZ 73728
#define MM_SMEM (2 * BUFSZ)

template <bool RELU, bool RES>
__global__ __launch_bounds__(256, 1) void k_gemm_mma(
    const float* __restrict__ A0, const float* __restrict__ A1,
    const __nv_bfloat16* __restrict__ wL,   // &g_wm[L * 2*8*2*8192]
    const float* __restrict__ bias, const float* __restrict__ resid,
    float* __restrict__ out) {
    extern __shared__ char sm[];
    uint32_t sb = smem_u32(sm);
    int tid = threadIdx.x, lane = tid & 31, warp = tid >> 5;
    int rowBlk = blockIdx.y * 128, cb = blockIdx.x;
    int wm = (warp >> 2) * 64, wn = (warp & 3) * 32;
    const __nv_bfloat16* wbase = wL + (size_t)cb * 8 * 2 * 8192;

    float acc[4][4][4];
#pragma unroll
    for (int a = 0; a < 4; a++)
#pragma unroll
        for (int b = 0; b < 4; b++)
#pragma unroll
            for (int c = 0; c < 4; c++) acc[a][b][c] = 0.f;

    // per-lane ldmatrix address components
    int aRow = (lane & 7) + ((lane >> 3) & 1) * 8;  // 0..15
    int aK   = (lane >> 4) * 8;                     // 0 | 8
    int l2   = lane & 15;
    int bN   = l2 & 7;
    int bK   = (l2 >> 3) * 8;

    auto issueB = [&](int sc, int buf) {
        const char* srcH = (const char*)(wbase + ((size_t)sc * 2 + 0) * 8192);
        const char* srcL = (const char*)(wbase + ((size_t)sc * 2 + 1) * 8192);
        uint32_t dB = sb + buf * BUFSZ + 36864;
#pragma unroll
        for (int u = 0; u < 4; u++) {
            int p = tid + (u << 8);        // 0..1023
            int n = p >> 3, seg = p & 7;
            cpa16(dB + n * ASTR + seg * 16,         srcH + n * 128 + seg * 16);
            cpa16(dB + 18432 + n * ASTR + seg * 16, srcL + n * 128 + seg * 16);
        }
        asm volatile("cp.async.commit_group;\n" ::);
    };
    auto loadA = [&](int sc, float4* v) {
        const float* A = (sc < 4) ? A0 : A1;
        int k0 = (sc & 3) << 6;
#pragma unroll
        for (int it = 0; it < 8; it++) {
            int p = tid + (it << 8);       // 0..2047
            int m = p >> 4, kq = p & 15;
            int row = rowBlk + m;
            v[it] = (row < NN) ? *(const float4*)(A + (size_t)row * HH + k0 + kq * 4)
                               : make_float4(0, 0, 0, 0);
        }
    };
    auto storeA = [&](float4* v, int buf) {
        char* dA = sm + buf * BUFSZ;
#pragma unroll
        for (int it = 0; it < 8; it++) {
            int p = tid + (it << 8);
            int m = p >> 4, kq = p & 15;
            float4 vv = v[it];
            union B4 { __nv_bfloat16 h[4]; uint2 u; };
            B4 hi, lo;
            hi.h[0] = __float2bfloat16(vv.x); hi.h[1] = __float2bfloat16(vv.y);
            hi.h[2] = __float2bfloat16(vv.z); hi.h[3] = __float2bfloat16(vv.w);
            lo.h[0] = __float2bfloat16(vv.x - __bfloat162float(hi.h[0]));
            lo.h[1] = __float2bfloat16(vv.y - __bfloat162float(hi.h[1]));
            lo.h[2] = __float2bfloat16(vv.z - __bfloat162float(hi.h[2]));
            lo.h[3] = __float2bfloat16(vv.w - __bfloat162float(hi.h[3]));
            *(uint2*)(dA + m * ASTR + kq * 8)         = hi.u;
            *(uint2*)(dA + 18432 + m * ASTR + kq * 8) = lo.u;
        }
    };

    float4 va[8];
    // prologue: fill buffer 0 with chunk 0, prefetch chunk 1 regs
    loadA(0, va);
    issueB(0, 0);
    storeA(va, 0);
    asm volatile("cp.async.wait_group 0;\n" ::);
    __syncthreads();
    loadA(1, va);

    for (int sc = 0; sc < 8; sc++) {
        int buf = sc & 1;
        if (sc < 7) {
            issueB(sc + 1, buf ^ 1);   // async B fill of other buffer
            storeA(va, buf ^ 1);       // A convert into other buffer
            if (sc < 6) loadA(sc + 2, va);   // prefetch next A regs
        }
        // --- compute 4 k16 steps from buf ---
        uint32_t bA = sb + buf * BUFSZ, bB = bA + 36864;
#pragma unroll
        for (int kt = 0; kt < 4; kt++) {
            uint32_t Ah[4][4], Al[4][4], Bh[4][2], Bl[4][2];
#pragma unroll
            for (int mi = 0; mi < 4; mi++) {
                uint32_t ad = bA + (uint32_t)(wm + mi * 16 + aRow) * ASTR + (kt * 16 + aK) * 2;
                ldmx4(Ah[mi][0], Ah[mi][1], Ah[mi][2], Ah[mi][3], ad);
                ldmx4(Al[mi][0], Al[mi][1], Al[mi][2], Al[mi][3], ad + 18432);
            }
#pragma unroll
            for (int ni = 0; ni < 4; ni++) {
                uint32_t bd = bB + (uint32_t)(wn + ni * 8 + bN) * ASTR + (kt * 16 + bK) * 2;
                ldmx2(Bh[ni][0], Bh[ni][1], bd);
                ldmx2(Bl[ni][0], Bl[ni][1], bd + 18432);
            }
#pragma unroll
            for (int mi = 0; mi < 4; mi++)
#pragma unroll
                for (int ni = 0; ni < 4; ni++) {
                    mma16816(acc[mi][ni], Ah[mi], Bh[ni]);
                    mma16816(acc[mi][ni], Al[mi], Bh[ni]);
                    mma16816(acc[mi][ni], Ah[mi], Bl[ni]);
                }
        }
        if (sc < 7) asm volatile("cp.async.wait_group 0;\n" ::);
        __syncthreads();
    }
    // --- epilogue ---
#pragma unroll
    for (int mi = 0; mi < 4; mi++) {
        int r0 = rowBlk + wm + mi * 16 + (lane >> 2);
        int r1 = r0 + 8;
#pragma unroll
        for (int ni = 0; ni < 4; ni++) {
            int col = cb * 128 + wn + ni * 8 + (lane & 3) * 2;
            float b0 = bias[col], b1 = bias[col + 1];
            float* c = acc[mi][ni];
            if (r0 < NN) {
                float v0 = c[0] + b0, v1 = c[1] + b1;
                if (RELU) { v0 = fmaxf(v0, 0.f); v1 = fmaxf(v1, 0.f); }
                if (RES) {
                    v0 = 0.5f * (resid[(size_t)r0 * HH + col] + v0);
                    v1 = 0.5f * (resid[(size_t)r0 * HH + col + 1] + v1);
                }
                *(float2*)(out + (size_t)r0 * HH + col) = make_float2(v0, v1);
            }
            if (r1 < NN) {
                float v2 = c[2] + b0, v3 = c[3] + b1;
                if (RELU) { v2 = fmaxf(v2, 0.f); v3 = fmaxf(v3, 0.f); }
                if (RES) {
                    v2 = 0.5f * (resid[(size_t)r1 * HH + col] + v2);
                    v3 = 0.5f * (resid[(size_t)r1 * HH + col + 1] + v3);
                }
                *(float2*)(out + (size_t)r1 * HH + col) = make_float2(v2, v3);
            }
        }
    }
}

// ---------------- final layer (C_OUT = 3) + fused y copy -------------------
__global__ void k_final(const float* __restrict__ W0, const float* __restrict__ W1,
                        const float* __restrict__ bf, float* __restrict__ out) {
    __shared__ float w0[HH * 3], w1[HH * 3];
    int tid = threadIdx.x;
    for (int i = tid; i < HH * 3; i += 256) { w0[i] = W0[i]; w1[i] = W1[i]; }
    __syncthreads();
    int warp = tid >> 5, lane = tid & 31;
    int node = blockIdx.x * 8 + warp;
    if (node >= NN) return;
    const float* y  = g_y  + (size_t)node * HH;
    const float* tx = g_tx + (size_t)node * HH;
    float* ycopy = out + NN * 3 + (size_t)node * HH;
    float p0 = 0.f, p1 = 0.f, p2 = 0.f;
#pragma unroll
    for (int u = 0; u < 8; u++) {
        int k = lane * 8 + u;
        float yv = y[k], tv = tx[k];
        ycopy[k] = yv;
        p0 += yv * w0[k * 3 + 0] + tv * w1[k * 3 + 0];
        p1 += yv * w0[k * 3 + 1] + tv * w1[k * 3 + 1];
        p2 += yv * w0[k * 3 + 2] + tv * w1[k * 3 + 2];
    }
#pragma unroll
    for (int o = 16; o > 0; o >>= 1) {
        p0 += __shfl_xor_sync(0xffffffffu, p0, o);
        p1 += __shfl_xor_sync(0xffffffffu, p1, o);
        p2 += __shfl_xor_sync(0xffffffffu, p2, o);
    }
    if (lane == 0) {
        out[node * 3 + 0] = p0 + bf[0];
        out[node * 3 + 1] = p1 + bf[1];
        out[node * 3 + 2] = p2 + bf[2];
    }
}

// ---------------- launch ---------------------------------------------------
extern "C" void kernel_launch(void* const* d_in, const int* in_sizes, int n_in,
                              void* d_out, int out_size) {
    (void)in_sizes; (void)n_in; (void)out_size;
    const float* x   = (const float*)d_in[0];
    const int*   ei  = (const int*)d_in[1];
    const float* Wi0 = (const float*)d_in[2];
    const float* Wi1 = (const float*)d_in[3];
    const float* bi  = (const float*)d_in[4];
    const float* Wr0 = (const float*)d_in[5];
    const float* Wr1 = (const float*)d_in[6];
    const float* br  = (const float*)d_in[7];
    const float* Wf0 = (const float*)d_in[8];
    const float* Wf1 = (const float*)d_in[9];
    const float* bf  = (const float*)d_in[10];
    float* out = (float*)d_out;

    float *py, *ph, *ptx;
    __nv_bfloat16* pwm;
    cudaGetSymbolAddress((void**)&py,  g_y);
    cudaGetSymbolAddress((void**)&ph,  g_h);
    cudaGetSymbolAddress((void**)&ptx, g_tx);
    cudaGetSymbolAddress((void**)&pwm, g_wm);

    cudaFuncSetAttribute(k_gemm_mma<true, false>, cudaFuncAttributeMaxDynamicSharedMemorySize, MM_SMEM);
    cudaFuncSetAttribute(k_gemm_mma<true, true>,  cudaFuncAttributeMaxDynamicSharedMemorySize, MM_SMEM);

    k_zero_deg<<<(NN + 255) / 256, 256>>>();
    k_hist<<<(EE + 255) / 256, 256>>>(ei);
    k_prepw_mm<<<(6 * 2 * 8 * 128 * 16 + 255) / 256, 256>>>(Wr0, Wr1);
    k_scan<<<1, 1024>>>();
    k_bucket<<<(EE + 255) / 256, 256>>>(ei);

    k_agg3<<<(NN + 255) / 256, 256>>>(x);
    k_lin0<<<(NN + 7) / 8, 256>>>(x, Wi0, Wi1, bi);

    dim3 ggrid(2, (NN + 127) / 128);
    int aggBlocks = (NN * 2) / 8;
    const size_t WMSZ = (size_t)2 * 8 * 2 * 8192;

    for (int blk = 0; blk < 3; blk++) {
        int L0 = 2 * blk, L1 = 2 * blk + 1;
        k_agg256<<<aggBlocks, 256>>>(py);
        k_gemm_mma<true, false><<<ggrid, 256, MM_SMEM>>>(py, ptx, pwm + (size_t)L0 * WMSZ, br + L0 * HH, nullptr, ph);
        k_agg256<<<aggBlocks, 256>>>(ph);
        k_gemm_mma<true, true><<<ggrid, 256, MM_SMEM>>>(ph, ptx, pwm + (size_t)L1 * WMSZ, br + L1 * HH, py, py);
    }
    k_agg256<<<aggBlocks, 256>>>(py);
    k_final<<<(NN + 7) / 8, 256>>>(Wf0, Wf1, bf, out);
}